// round 16
// baseline (speedup 1.0000x reference)
#include <cuda_runtime.h>
#include <cuda_fp16.h>
#include <cstdint>

#define NUM_U 200000
#define NUM_I 100000
#define NUM_E 500000
#define DIM_D 128
#define DIM_H 256
#define DIM_O 128
#define CAP_U 64    // max edges per user (mean 2.5; Poisson tail ~0 at 64)
#define CAP_I 128   // max edges per item (mean 5.0; Poisson tail ~0 at 128)
#define NI_TILES 782   // cdiv(NUM_I,128)
#define NU_TILES 1563  // cdiv(NUM_U,128)

// ---------------- scratch (device globals; no allocation allowed) ----------
__device__ __align__(16) float g_r_u[(size_t)NUM_U * 128];  // h_u@Wr2_iu + b
__device__ __align__(16) float g_r_i[(size_t)NUM_I * 128];  // h_i@Wr2_ui + b
__device__ int g_cnt_u[NUM_U];
__device__ int g_cnt_i[NUM_I];
__device__ __align__(16) int g_adj_u[(size_t)NUM_U * CAP_U];   // user's item nbrs
__device__ __align__(16) int g_adj_i[(size_t)NUM_I * CAP_I];   // item's user nbrs
// fp16 activations (single-rounded)
__device__ __align__(16) uint16_t g_xf_u[(size_t)NUM_U * 128];
__device__ __align__(16) uint16_t g_xf_i[(size_t)NUM_I * 128];
__device__ __align__(16) uint16_t g_a1f_u[(size_t)NUM_U * 128];
__device__ __align__(16) uint16_t g_a1f_i[(size_t)NUM_I * 128];
__device__ __align__(16) uint16_t g_pf_u[(size_t)NUM_U * 128];  // fp16(h_u @ Wl2_ui)
__device__ __align__(16) uint16_t g_pf_i[(size_t)NUM_I * 128];  // fp16(h_i @ Wl2_iu)
// transposed fp16 weights, [N][K] layout:
// 0:Wl1_ui 32768:Wr1_ui 65536:Wl1_iu 98304:Wr1_iu
// 131072:[Wl2_ui;Wr2_iu] (user combo)  196608:[Wl2_iu;Wr2_ui] (item combo)
__device__ __align__(16) uint16_t g_wT[262144];

// ---------------- merged x convert + cnt zero -------------------------------
__global__ void cvt_zero_kernel(const float4* __restrict__ inU, uint2* __restrict__ ofU,
                                const float4* __restrict__ inI, uint2* __restrict__ ofI,
                                int* __restrict__ cnt_u, int* __restrict__ cnt_i) {
    int i = blockIdx.x * blockDim.x + threadIdx.x;
    const int nU = NUM_U * 32, nI = NUM_I * 32;
    if (i < nU + nI) {
        const float4* in = (i < nU) ? inU : inI;
        uint2* of = (i < nU) ? ofU : ofI;
        int j = (i < nU) ? i : i - nU;
        float4 v = in[j];
        __half2 p01 = __float22half2_rn(make_float2(v.x, v.y));
        __half2 p23 = __float22half2_rn(make_float2(v.z, v.w));
        of[j] = make_uint2(*reinterpret_cast<uint32_t*>(&p01),
                           *reinterpret_cast<uint32_t*>(&p23));
    } else {
        int k = i - (nU + nI);
        if (k < NUM_U) cnt_u[k] = 0;
        else if (k < NUM_U + NUM_I) cnt_i[k - NUM_U] = 0;
    }
}

// ---------------- adjacency-bucket build ------------------------------------
__global__ void fill_adj(const int* __restrict__ src, const int* __restrict__ dst,
                         int* __restrict__ cnt_u, int* __restrict__ cnt_i,
                         int* __restrict__ adj_u, int* __restrict__ adj_i) {
    int e = blockIdx.x * blockDim.x + threadIdx.x;
    if (e >= NUM_E) return;
    int s = src[e], d = dst[e];
    int pu = atomicAdd(cnt_u + s, 1);
    if (pu < CAP_U) adj_u[(size_t)s * CAP_U + pu] = d;
    int pi = atomicAdd(cnt_i + d, 1);
    if (pi < CAP_I) adj_i[(size_t)d * CAP_I + pi] = s;
}

// ---------------- gather-mean core (device), unroll-4 for MLP ---------------
__device__ __forceinline__ void gm_core(const uint16_t* __restrict__ feat,
                                        const int* __restrict__ adj,
                                        const int* __restrict__ cnt,
                                        int cap, int node, int lane,
                                        uint16_t* __restrict__ outH,
                                        float* __restrict__ outF,
                                        const float* __restrict__ add) {
    int c = cnt[node];
    int cc = min(c, cap);
    float a0 = 0.f, a1 = 0.f, a2 = 0.f, a3 = 0.f;
    float a4 = 0.f, a5 = 0.f, a6 = 0.f, a7 = 0.f;
    const int* ap = adj + (size_t)node * cap;
    int e = 0;
    for (; e + 4 <= cc; e += 4) {
        int i0 = __ldg(ap + e + 0), i1 = __ldg(ap + e + 1);
        int i2 = __ldg(ap + e + 2), i3 = __ldg(ap + e + 3);
        uint4 v0 = *reinterpret_cast<const uint4*>(feat + (size_t)i0 * 128 + lane * 8);
        uint4 v1 = *reinterpret_cast<const uint4*>(feat + (size_t)i1 * 128 + lane * 8);
        uint4 v2 = *reinterpret_cast<const uint4*>(feat + (size_t)i2 * 128 + lane * 8);
        uint4 v3 = *reinterpret_cast<const uint4*>(feat + (size_t)i3 * 128 + lane * 8);
#define GM_ACC(v)                                                             \
        {                                                                     \
            float2 f0 = __half22float2(*reinterpret_cast<__half2*>(&(v).x));  \
            float2 f1 = __half22float2(*reinterpret_cast<__half2*>(&(v).y));  \
            float2 f2 = __half22float2(*reinterpret_cast<__half2*>(&(v).z));  \
            float2 f3 = __half22float2(*reinterpret_cast<__half2*>(&(v).w));  \
            a0 += f0.x; a1 += f0.y; a2 += f1.x; a3 += f1.y;                   \
            a4 += f2.x; a5 += f2.y; a6 += f3.x; a7 += f3.y;                   \
        }
        GM_ACC(v0) GM_ACC(v1) GM_ACC(v2) GM_ACC(v3)
    }
    for (; e < cc; ++e) {
        int idx = __ldg(ap + e);
        uint4 v = *reinterpret_cast<const uint4*>(feat + (size_t)idx * 128 + lane * 8);
        GM_ACC(v)
    }
#undef GM_ACC
    float s = 1.f / (float)max(c, 1);
    a0 *= s; a1 *= s; a2 *= s; a3 *= s; a4 *= s; a5 *= s; a6 *= s; a7 *= s;
    const size_t off = (size_t)node * 128 + lane * 8;
    if (outH) {
        __half2 h0 = __float22half2_rn(make_float2(a0, a1));
        __half2 h1 = __float22half2_rn(make_float2(a2, a3));
        __half2 h2 = __float22half2_rn(make_float2(a4, a5));
        __half2 h3 = __float22half2_rn(make_float2(a6, a7));
        uint4 o;
        o.x = *reinterpret_cast<uint32_t*>(&h0);
        o.y = *reinterpret_cast<uint32_t*>(&h1);
        o.z = *reinterpret_cast<uint32_t*>(&h2);
        o.w = *reinterpret_cast<uint32_t*>(&h3);
        *reinterpret_cast<uint4*>(outH + off) = o;
    } else {
        float4 r0 = *reinterpret_cast<const float4*>(add + off);
        float4 r1 = *reinterpret_cast<const float4*>(add + off + 4);
        float4 o0, o1;
        o0.x = fmaxf(r0.x + a0, 0.f); o0.y = fmaxf(r0.y + a1, 0.f);
        o0.z = fmaxf(r0.z + a2, 0.f); o0.w = fmaxf(r0.w + a3, 0.f);
        o1.x = fmaxf(r1.x + a4, 0.f); o1.y = fmaxf(r1.y + a5, 0.f);
        o1.z = fmaxf(r1.z + a6, 0.f); o1.w = fmaxf(r1.w + a7, 0.f);
        *reinterpret_cast<float4*>(outF + off) = o0;
        *reinterpret_cast<float4*>(outF + off + 4) = o1;
    }
}

// ---------------- merged gather: items then users in one grid ---------------
__global__ void gather2(const uint16_t* __restrict__ featI,
                        uint16_t* __restrict__ outHI, float* __restrict__ outFI,
                        const float* __restrict__ addI,
                        const uint16_t* __restrict__ featU,
                        uint16_t* __restrict__ outHU, float* __restrict__ outFU,
                        const float* __restrict__ addU,
                        const int* __restrict__ adj_i, const int* __restrict__ cnt_i,
                        const int* __restrict__ adj_u, const int* __restrict__ cnt_u) {
    int t = blockIdx.x * blockDim.x + threadIdx.x;
    int lane = t & 15;
    int idx = t >> 4;
    if (idx < NUM_I) {
        gm_core(featI, adj_i, cnt_i, CAP_I, idx, lane, outHI, outFI, addI);
    } else if (idx < NUM_I + NUM_U) {
        gm_core(featU, adj_u, cnt_u, CAP_U, idx - NUM_I, lane, outHU, outFU, addU);
    }
}

// ---------------- merged weight prep: all 8 matrices in one launch ----------
__global__ void prep_all(const float* __restrict__ W0, const float* __restrict__ W1,
                         const float* __restrict__ W2, const float* __restrict__ W3,
                         const float* __restrict__ W4, const float* __restrict__ W5,
                         const float* __restrict__ W6, const float* __restrict__ W7,
                         uint16_t* __restrict__ wT) {
    int idx = blockIdx.x * blockDim.x + threadIdx.x;
    if (idx >= 262144) return;
    int m = idx >> 15, within = idx & 32767;
    const float* W;
    int N;
    switch (m) {
        case 0: W = W0; N = 256; break;
        case 1: W = W1; N = 256; break;
        case 2: W = W2; N = 256; break;
        case 3: W = W3; N = 256; break;
        case 4: W = W4; N = 128; break;
        case 5: W = W5; N = 128; break;
        case 6: W = W6; N = 128; break;
        default: W = W7; N = 128; break;
    }
    int K = 32768 / N;
    int k = within / N, n = within % N;
    __half h = __float2half_rn(W[within]);
    wT[(m << 15) + n * K + k] = *reinterpret_cast<uint16_t*>(&h);
}

// ---------------- mma.sync helpers ------------------------------------------
__device__ __forceinline__ uint32_t smem_u32(const void* p) {
    uint32_t a;
    asm("{ .reg .u64 t; cvta.to.shared.u64 t, %1; cvt.u32.u64 %0, t; }"
        : "=r"(a) : "l"(p));
    return a;
}
__device__ __forceinline__ void ldm_x4(uint32_t addr, uint32_t& r0, uint32_t& r1,
                                       uint32_t& r2, uint32_t& r3) {
    asm volatile("ldmatrix.sync.aligned.m8n8.x4.shared.b16 {%0,%1,%2,%3}, [%4];"
                 : "=r"(r0), "=r"(r1), "=r"(r2), "=r"(r3) : "r"(addr));
}
__device__ __forceinline__ void mma_f16(float* c, const uint32_t* a,
                                        const uint32_t* b) {
    asm volatile(
        "mma.sync.aligned.m16n8k16.row.col.f32.f16.f16.f32 "
        "{%0,%1,%2,%3}, {%4,%5,%6,%7}, {%8,%9}, {%0,%1,%2,%3};"
        : "+f"(c[0]), "+f"(c[1]), "+f"(c[2]), "+f"(c[3])
        : "r"(a[0]), "r"(a[1]), "r"(a[2]), "r"(a[3]), "r"(b[0]), "r"(b[1]));
}
__device__ __forceinline__ void cp16(uint32_t dst, const void* src, int sz) {
    asm volatile("cp.async.cg.shared.global [%0], [%1], 16, %2;"
                 :: "r"(dst), "l"(src), "r"(sz) : "memory");
}

// ---------------- mega GEMM (items + users merged into one grid) ------------
// blockIdx.y < NI_TILES -> item tile; else user tile.
//  Stage A: h[128,256] = relu(A0@W1l + A1@W1r + b1), kept in SMEM (fp16).
//  Stage B: pf = fp16(h @ Wc[0:128]); r = h @ Wc[128:256] + b2 (fp32).
#define SROW2 40                     // staging: fp16/row (32 + 8 pad)
#define ATILE2 (128 * SROW2 * 2)     // 10240 B per operand tile
#define STAGE2 (2 * ATILE2)          // A + B per buffer = 20480
#define HROW 264                     // h smem row: 256 + 8 pad (fp16)
#define H_BYTES (128 * HROW * 2)     // 67584
#define MEGA_SMEM (H_BYTES + 2 * STAGE2)  // 108544 -> 2 CTAs/SM
__global__ void __launch_bounds__(256, 2)
mega_gemm_all(const uint16_t* __restrict__ a1f_i, const uint16_t* __restrict__ xf_i,
              const uint16_t* __restrict__ a1f_u, const uint16_t* __restrict__ xf_u,
              const uint16_t* __restrict__ wT,
              const float* __restrict__ b1I, const float* __restrict__ b2I,
              const float* __restrict__ b1U, const float* __restrict__ b2U,
              uint16_t* __restrict__ pf_i, float* __restrict__ r_i,
              uint16_t* __restrict__ pf_u, float* __restrict__ r_u) {
    extern __shared__ __align__(16) uint16_t smem[];
    const uint32_t hbase = smem_u32(smem);
    const uint32_t stage = hbase + H_BYTES;

    const bool isItem = blockIdx.y < NI_TILES;
    const int rowBase = (isItem ? blockIdx.y : blockIdx.y - NI_TILES) * 128;
    const int M = isItem ? NUM_I : NUM_U;
    const uint16_t* A0 = isItem ? a1f_i : a1f_u;
    const uint16_t* A1 = isItem ? xf_i : xf_u;
    const uint16_t* W1l = wT + (isItem ? 0 : 65536);
    const uint16_t* W1r = wT + (isItem ? 32768 : 98304);
    const uint16_t* Wc = wT + (isItem ? 196608 : 131072);
    const float* b1 = isItem ? b1I : b1U;
    const float* b2 = isItem ? b2I : b2U;
    uint16_t* Pf = isItem ? pf_i : pf_u;
    float* R = isItem ? r_i : r_u;

    const int tid = threadIdx.x;
    const int wid = tid >> 5, lane = tid & 31;
    const int wm = wid >> 2, wn = wid & 3;

    const int ldR0 = tid >> 2;        // 0..63, rows step 64
    const int ldS = tid & 3;          // 4 segs of 8 fp16

    const int aRow = lane & 15, aColH = (lane >> 4) * 8;
    const int bRow = ((lane >> 4) & 1) * 8 + (lane & 7);
    const int bColH = ((lane >> 3) & 1) * 8;
    const int qr = lane >> 2, qc = lane & 3;

    float acc[4][4][4];

    // ================= Stage A: h = relu(A0@W1l + A1@W1r + b1) ==============
#pragma unroll 1
    for (int half = 0; half < 2; ++half) {
#pragma unroll
        for (int i = 0; i < 4; ++i)
#pragma unroll
            for (int j = 0; j < 4; ++j)
#pragma unroll
                for (int k = 0; k < 4; ++k) acc[i][j][k] = 0.f;

        auto issueA = [&](int c) {   // c in 0..7: phase = c>>2, k0 = (c&3)*32
            const int phase = c >> 2;
            const int k0 = (c & 3) * 32;
            const uint16_t* a = phase ? A1 : A0;
            const uint16_t* w = phase ? W1r : W1l;
            const uint32_t st = stage + (c & 1) * STAGE2;
#pragma unroll
            for (int it = 0; it < 2; ++it) {
                const int r = ldR0 + it * 64;
                const uint32_t doff = r * (SROW2 * 2) + ldS * 16;
                const int grow = rowBase + r;
                const int sz = (grow < M) ? 16 : 0;
                cp16(st + doff,
                     a + (size_t)(grow < M ? grow : 0) * 128 + k0 + ldS * 8, sz);
                cp16(st + ATILE2 + doff,
                     w + (size_t)(half * 128 + r) * 128 + k0 + ldS * 8, 16);
            }
            asm volatile("cp.async.commit_group;" ::: "memory");
        };

        issueA(0);
        issueA(1);
        for (int c = 0; c < 8; ++c) {
            if (c < 7) asm volatile("cp.async.wait_group 1;" ::: "memory");
            else       asm volatile("cp.async.wait_group 0;" ::: "memory");
            __syncthreads();
            const uint32_t st = stage + (c & 1) * STAGE2;
#pragma unroll
            for (int ks = 0; ks < 2; ++ks) {
                const int kk = ks * 16;
                uint32_t af[4][4];
#pragma unroll
                for (int fm = 0; fm < 4; ++fm) {
                    uint32_t off = st + 2u * ((wm * 64 + fm * 16 + aRow) * SROW2 + kk + aColH);
                    ldm_x4(off, af[fm][0], af[fm][1], af[fm][2], af[fm][3]);
                }
                uint32_t bf[4][2];
#pragma unroll
                for (int g = 0; g < 2; ++g) {
                    uint32_t off = st + ATILE2 +
                                   2u * ((wn * 32 + g * 16 + bRow) * SROW2 + kk + bColH);
                    ldm_x4(off, bf[2 * g][0], bf[2 * g][1],
                           bf[2 * g + 1][0], bf[2 * g + 1][1]);
                }
#pragma unroll
                for (int fm = 0; fm < 4; ++fm)
#pragma unroll
                    for (int fn = 0; fn < 4; ++fn)
                        mma_f16(acc[fm][fn], af[fm], bf[fn]);
            }
            __syncthreads();
            if (c + 2 < 8) issueA(c + 2);
        }

        // epilogue: relu(acc + b1) -> h smem (fp16)
#pragma unroll
        for (int fm = 0; fm < 4; ++fm) {
            const int row0 = wm * 64 + fm * 16 + qr;
#pragma unroll
            for (int fn = 0; fn < 4; ++fn) {
                const int colh = wn * 32 + fn * 8 + qc * 2;
                const int col = half * 128 + colh;
                const float bx = b1[col], by = b1[col + 1];
#pragma unroll
                for (int hh = 0; hh < 2; ++hh) {
                    const int row = row0 + hh * 8;
                    float vx = fmaxf(acc[fm][fn][hh * 2 + 0] + bx, 0.f);
                    float vy = fmaxf(acc[fm][fn][hh * 2 + 1] + by, 0.f);
                    __half2 hp = __float22half2_rn(make_float2(vx, vy));
                    uint32_t addr = hbase + 2u * (row * HROW + col);
                    asm volatile("st.shared.b32 [%0], %1;"
                                 :: "r"(addr), "r"(*reinterpret_cast<uint32_t*>(&hp))
                                 : "memory");
                }
            }
        }
    }
    __syncthreads();  // h complete

    // ================= Stage B: [pf | r] = h @ Wc ============================
#pragma unroll 1
    for (int half = 0; half < 2; ++half) {
#pragma unroll
        for (int i = 0; i < 4; ++i)
#pragma unroll
            for (int j = 0; j < 4; ++j)
#pragma unroll
                for (int k = 0; k < 4; ++k) acc[i][j][k] = 0.f;

        auto issueB = [&](int c) {   // c in 0..7: k0 = c*32 over K=256
            const int k0 = c * 32;
            const uint32_t st = stage + (c & 1) * STAGE2;
#pragma unroll
            for (int it = 0; it < 2; ++it) {
                const int r = ldR0 + it * 64;
                const uint32_t doff = r * (SROW2 * 2) + ldS * 16;
                cp16(st + ATILE2 + doff,
                     Wc + (size_t)(half * 128 + r) * 256 + k0 + ldS * 8, 16);
            }
            asm volatile("cp.async.commit_group;" ::: "memory");
        };

        issueB(0);
        issueB(1);
        for (int c = 0; c < 8; ++c) {
            if (c < 7) asm volatile("cp.async.wait_group 1;" ::: "memory");
            else       asm volatile("cp.async.wait_group 0;" ::: "memory");
            __syncthreads();
            const uint32_t st = stage + (c & 1) * STAGE2;
#pragma unroll
            for (int ks = 0; ks < 2; ++ks) {
                const int kkg = c * 32 + ks * 16;
                uint32_t af[4][4];
#pragma unroll
                for (int fm = 0; fm < 4; ++fm) {
                    uint32_t off = hbase + 2u * ((wm * 64 + fm * 16 + aRow) * HROW + kkg + aColH);
                    ldm_x4(off, af[fm][0], af[fm][1], af[fm][2], af[fm][3]);
                }
                uint32_t bf[4][2];
#pragma unroll
                for (int g = 0; g < 2; ++g) {
                    uint32_t off = st + ATILE2 +
                                   2u * ((wn * 32 + g * 16 + bRow) * SROW2 + ks * 16 + bColH);
                    ldm_x4(off, bf[2 * g][0], bf[2 * g][1],
                           bf[2 * g + 1][0], bf[2 * g + 1][1]);
                }
#pragma unroll
                for (int fm = 0; fm < 4; ++fm)
#pragma unroll
                    for (int fn = 0; fn < 4; ++fn)
                        mma_f16(acc[fm][fn], af[fm], bf[fn]);
            }
            __syncthreads();
            if (c + 2 < 8) issueB(c + 2);
        }

        // epilogue: half0 -> pf (fp16, no bias); half1 -> r (fp32, + b2)
#pragma unroll
        for (int fm = 0; fm < 4; ++fm) {
            const int r0 = rowBase + wm * 64 + fm * 16 + qr;
#pragma unroll
            for (int fn = 0; fn < 4; ++fn) {
                const int colh = wn * 32 + fn * 8 + qc * 2;
#pragma unroll
                for (int hh = 0; hh < 2; ++hh) {
                    const int rr = r0 + hh * 8;
                    if (rr >= M) continue;
                    float vx = acc[fm][fn][hh * 2 + 0];
                    float vy = acc[fm][fn][hh * 2 + 1];
                    if (half == 0) {
                        __half2 hp = __float22half2_rn(make_float2(vx, vy));
                        *(uint32_t*)(Pf + (size_t)rr * 128 + colh) =
                            *reinterpret_cast<uint32_t*>(&hp);
                    } else {
                        *(float2*)(R + (size_t)rr * 128 + colh) =
                            make_float2(vx + b2[colh], vy + b2[colh + 1]);
                    }
                }
            }
        }
    }
}

// ---------------- host launch ------------------------------------------------
static inline int cdiv(int a, int b) { return (a + b - 1) / b; }

extern "C" void kernel_launch(void* const* d_in, const int* in_sizes, int n_in,
                              void* d_out, int out_size) {
    const float* x_user = (const float*)d_in[0];
    const float* x_item = (const float*)d_in[1];
    const int* e_src = (const int*)d_in[2];
    const int* e_dst = (const int*)d_in[3];
    const float* Wl1_ui = (const float*)d_in[4];
    const float* Wr1_ui = (const float*)d_in[5];
    const float* bl1_ui = (const float*)d_in[6];
    const float* Wl1_iu = (const float*)d_in[7];
    const float* Wr1_iu = (const float*)d_in[8];
    const float* bl1_iu = (const float*)d_in[9];
    const float* Wl2_ui = (const float*)d_in[10];
    const float* Wr2_ui = (const float*)d_in[11];
    const float* bl2_ui = (const float*)d_in[12];
    const float* Wl2_iu = (const float*)d_in[13];
    const float* Wr2_iu = (const float*)d_in[14];
    const float* bl2_iu = (const float*)d_in[15];
    float* out = (float*)d_out;

    float *r_u, *r_i;
    int *cnt_u, *cnt_i, *adj_u, *adj_i;
    uint16_t *xf_u, *xf_i, *a1f_u, *a1f_i, *pf_u, *pf_i, *wT;
    cudaGetSymbolAddress((void**)&r_u, g_r_u);
    cudaGetSymbolAddress((void**)&r_i, g_r_i);
    cudaGetSymbolAddress((void**)&cnt_u, g_cnt_u);
    cudaGetSymbolAddress((void**)&cnt_i, g_cnt_i);
    cudaGetSymbolAddress((void**)&adj_u, g_adj_u);
    cudaGetSymbolAddress((void**)&adj_i, g_adj_i);
    cudaGetSymbolAddress((void**)&xf_u, g_xf_u);
    cudaGetSymbolAddress((void**)&xf_i, g_xf_i);
    cudaGetSymbolAddress((void**)&a1f_u, g_a1f_u);
    cudaGetSymbolAddress((void**)&a1f_i, g_a1f_i);
    cudaGetSymbolAddress((void**)&pf_u, g_pf_u);
    cudaGetSymbolAddress((void**)&pf_i, g_pf_i);
    cudaGetSymbolAddress((void**)&wT, g_wT);

    cudaFuncSetAttribute(mega_gemm_all, cudaFuncAttributeMaxDynamicSharedMemorySize,
                         MEGA_SMEM);

    const int TB = 256;

    // 1: x converts + cnt zero (merged)
    cvt_zero_kernel<<<cdiv((NUM_U + NUM_I) * 32 + NUM_U + NUM_I, TB), TB>>>(
        (const float4*)x_user, (uint2*)xf_u, (const float4*)x_item, (uint2*)xf_i,
        cnt_u, cnt_i);
    // 2: adjacency fill
    fill_adj<<<cdiv(NUM_E, TB), TB>>>(e_src, e_dst, cnt_u, cnt_i, adj_u, adj_i);
    // 3: weight prep (merged, 8 matrices)
    prep_all<<<cdiv(262144, TB), TB>>>(Wl1_ui, Wr1_ui, Wl1_iu, Wr1_iu,
                                       Wl2_ui, Wr2_iu, Wl2_iu, Wr2_ui, wT);
    // 4: layer-1 gather-mean, items + users in one launch
    gather2<<<cdiv((NUM_I + NUM_U) * 16, TB), TB>>>(
        xf_u, a1f_i, nullptr, nullptr,
        xf_i, a1f_u, nullptr, nullptr,
        adj_i, cnt_i, adj_u, cnt_u);
    // 5: mega GEMM, items + users in one launch
    {
        dim3 g(1, NI_TILES + NU_TILES);
        mega_gemm_all<<<g, 256, MEGA_SMEM>>>(a1f_i, xf_i, a1f_u, xf_u, wT,
                                             bl1_ui, bl2_ui, bl1_iu, bl2_iu,
                                             pf_i, r_i, pf_u, r_u);
    }
    // 6: layer-2 gather + add + relu, items + users in one launch
    gather2<<<cdiv((NUM_I + NUM_U) * 16, TB), TB>>>(
        pf_u, nullptr, out + (size_t)NUM_U * DIM_O, r_i,
        pf_i, nullptr, out, r_u,
        adj_i, cnt_i, adj_u, cnt_u);
}

// round 17
// speedup vs baseline: 1.0672x; 1.0672x over previous
#include <cuda_runtime.h>
#include <cuda_fp16.h>
#include <cstdint>

#define NUM_U 200000
#define NUM_I 100000
#define NUM_E 500000
#define DIM_D 128
#define DIM_H 256
#define DIM_O 128
#define CAP_U 64    // max edges per user (mean 2.5; Poisson tail ~0 at 64)
#define CAP_I 128   // max edges per item (mean 5.0; Poisson tail ~0 at 128)

// ---------------- scratch (device globals; no allocation allowed) ----------
__device__ __align__(16) float g_r_u[(size_t)NUM_U * 128];  // h_u@Wr2_iu + b
__device__ __align__(16) float g_r_i[(size_t)NUM_I * 128];  // h_i@Wr2_ui + b
__device__ int g_cnt_u[NUM_U];
__device__ int g_cnt_i[NUM_I];
__device__ __align__(16) int g_adj_u[(size_t)NUM_U * CAP_U];   // user's item nbrs
__device__ __align__(16) int g_adj_i[(size_t)NUM_I * CAP_I];   // item's user nbrs
// fp16 activations (single-rounded)
__device__ __align__(16) uint16_t g_xf_u[(size_t)NUM_U * 128];
__device__ __align__(16) uint16_t g_xf_i[(size_t)NUM_I * 128];
__device__ __align__(16) uint16_t g_a1f_u[(size_t)NUM_U * 128];
__device__ __align__(16) uint16_t g_a1f_i[(size_t)NUM_I * 128];
__device__ __align__(16) uint16_t g_pf_u[(size_t)NUM_U * 128];  // fp16(h_u @ Wl2_ui)
__device__ __align__(16) uint16_t g_pf_i[(size_t)NUM_I * 128];  // fp16(h_i @ Wl2_iu)
// transposed fp16 weights, [N][K] layout:
// 0:Wl1_ui 32768:Wr1_ui 65536:Wl1_iu 98304:Wr1_iu
// 131072:[Wl2_ui;Wr2_iu] (user combo)  196608:[Wl2_iu;Wr2_ui] (item combo)
__device__ __align__(16) uint16_t g_wT[262144];

// ---------------- merged zero (two int arrays) ------------------------------
__global__ void zero2_kernel(int* __restrict__ a, int na, int* __restrict__ b, int nb) {
    int i = blockIdx.x * blockDim.x + threadIdx.x;
    if (i < na) a[i] = 0;
    else if (i < na + nb) b[i - na] = 0;
}

// ---------------- merged fp32 -> fp16 convert (x_user + x_item) -------------
__global__ void cvt2_kernel(const float4* __restrict__ inU, uint2* __restrict__ ofU,
                            const float4* __restrict__ inI, uint2* __restrict__ ofI) {
    int i = blockIdx.x * blockDim.x + threadIdx.x;
    const int nU = NUM_U * 32;
    const float4* in;
    uint2* of;
    int j;
    if (i < nU) { in = inU; of = ofU; j = i; }
    else if (i < nU + NUM_I * 32) { in = inI; of = ofI; j = i - nU; }
    else return;
    float4 v = in[j];
    __half2 p01 = __float22half2_rn(make_float2(v.x, v.y));
    __half2 p23 = __float22half2_rn(make_float2(v.z, v.w));
    of[j] = make_uint2(*reinterpret_cast<uint32_t*>(&p01),
                       *reinterpret_cast<uint32_t*>(&p23));
}

// ---------------- adjacency-bucket build ------------------------------------
__global__ void fill_adj(const int* __restrict__ src, const int* __restrict__ dst,
                         int* __restrict__ cnt_u, int* __restrict__ cnt_i,
                         int* __restrict__ adj_u, int* __restrict__ adj_i) {
    int e = blockIdx.x * blockDim.x + threadIdx.x;
    if (e >= NUM_E) return;
    int s = src[e], d = dst[e];
    int pu = atomicAdd(cnt_u + s, 1);
    if (pu < CAP_U) adj_u[(size_t)s * CAP_U + pu] = d;
    int pi = atomicAdd(cnt_i + d, 1);
    if (pi < CAP_I) adj_i[(size_t)d * CAP_I + pi] = s;
}

// ---------------- gather-mean core (device), unroll-2 for MLP ---------------
__device__ __forceinline__ void gm_core(const uint16_t* __restrict__ feat,
                                        const int* __restrict__ adj,
                                        const int* __restrict__ cnt,
                                        int cap, int node, int lane,
                                        uint16_t* __restrict__ outH,
                                        float* __restrict__ outF,
                                        const float* __restrict__ add) {
    int c = cnt[node];
    int cc = min(c, cap);
    float a0 = 0.f, a1 = 0.f, a2 = 0.f, a3 = 0.f;
    float a4 = 0.f, a5 = 0.f, a6 = 0.f, a7 = 0.f;
    const int* ap = adj + (size_t)node * cap;
#define GM_ACC(v)                                                             \
    {                                                                         \
        float2 f0 = __half22float2(*reinterpret_cast<__half2*>(&(v).x));      \
        float2 f1 = __half22float2(*reinterpret_cast<__half2*>(&(v).y));      \
        float2 f2 = __half22float2(*reinterpret_cast<__half2*>(&(v).z));      \
        float2 f3 = __half22float2(*reinterpret_cast<__half2*>(&(v).w));      \
        a0 += f0.x; a1 += f0.y; a2 += f1.x; a3 += f1.y;                       \
        a4 += f2.x; a5 += f2.y; a6 += f3.x; a7 += f3.y;                       \
    }
    int e = 0;
    for (; e + 2 <= cc; e += 2) {
        int i0 = __ldg(ap + e + 0), i1 = __ldg(ap + e + 1);
        uint4 v0 = *reinterpret_cast<const uint4*>(feat + (size_t)i0 * 128 + lane * 8);
        uint4 v1 = *reinterpret_cast<const uint4*>(feat + (size_t)i1 * 128 + lane * 8);
        GM_ACC(v0) GM_ACC(v1)
    }
    if (e < cc) {
        int idx = __ldg(ap + e);
        uint4 v = *reinterpret_cast<const uint4*>(feat + (size_t)idx * 128 + lane * 8);
        GM_ACC(v)
    }
#undef GM_ACC
    float s = 1.f / (float)max(c, 1);
    a0 *= s; a1 *= s; a2 *= s; a3 *= s; a4 *= s; a5 *= s; a6 *= s; a7 *= s;
    const size_t off = (size_t)node * 128 + lane * 8;
    if (outH) {
        __half2 h0 = __float22half2_rn(make_float2(a0, a1));
        __half2 h1 = __float22half2_rn(make_float2(a2, a3));
        __half2 h2 = __float22half2_rn(make_float2(a4, a5));
        __half2 h3 = __float22half2_rn(make_float2(a6, a7));
        uint4 o;
        o.x = *reinterpret_cast<uint32_t*>(&h0);
        o.y = *reinterpret_cast<uint32_t*>(&h1);
        o.z = *reinterpret_cast<uint32_t*>(&h2);
        o.w = *reinterpret_cast<uint32_t*>(&h3);
        *reinterpret_cast<uint4*>(outH + off) = o;
    } else {
        float4 r0 = *reinterpret_cast<const float4*>(add + off);
        float4 r1 = *reinterpret_cast<const float4*>(add + off + 4);
        float4 o0, o1;
        o0.x = fmaxf(r0.x + a0, 0.f); o0.y = fmaxf(r0.y + a1, 0.f);
        o0.z = fmaxf(r0.z + a2, 0.f); o0.w = fmaxf(r0.w + a3, 0.f);
        o1.x = fmaxf(r1.x + a4, 0.f); o1.y = fmaxf(r1.y + a5, 0.f);
        o1.z = fmaxf(r1.z + a6, 0.f); o1.w = fmaxf(r1.w + a7, 0.f);
        *reinterpret_cast<float4*>(outF + off) = o0;
        *reinterpret_cast<float4*>(outF + off + 4) = o1;
    }
}

// ---------------- merged gather: items then users in one grid ---------------
__global__ void gather2(const uint16_t* __restrict__ featI,
                        uint16_t* __restrict__ outHI, float* __restrict__ outFI,
                        const float* __restrict__ addI,
                        const uint16_t* __restrict__ featU,
                        uint16_t* __restrict__ outHU, float* __restrict__ outFU,
                        const float* __restrict__ addU,
                        const int* __restrict__ adj_i, const int* __restrict__ cnt_i,
                        const int* __restrict__ adj_u, const int* __restrict__ cnt_u) {
    int t = blockIdx.x * blockDim.x + threadIdx.x;
    int lane = t & 15;
    int idx = t >> 4;
    if (idx < NUM_I) {
        gm_core(featI, adj_i, cnt_i, CAP_I, idx, lane, outHI, outFI, addI);
    } else if (idx < NUM_I + NUM_U) {
        gm_core(featU, adj_u, cnt_u, CAP_U, idx - NUM_I, lane, outHU, outFU, addU);
    }
}

// ---------------- merged weight prep: all 8 matrices in one launch ----------
__global__ void prep_all(const float* __restrict__ W0, const float* __restrict__ W1,
                         const float* __restrict__ W2, const float* __restrict__ W3,
                         const float* __restrict__ W4, const float* __restrict__ W5,
                         const float* __restrict__ W6, const float* __restrict__ W7,
                         uint16_t* __restrict__ wT) {
    int idx = blockIdx.x * blockDim.x + threadIdx.x;
    if (idx >= 262144) return;
    int m = idx >> 15, within = idx & 32767;
    const float* W;
    int N;
    switch (m) {
        case 0: W = W0; N = 256; break;
        case 1: W = W1; N = 256; break;
        case 2: W = W2; N = 256; break;
        case 3: W = W3; N = 256; break;
        case 4: W = W4; N = 128; break;
        case 5: W = W5; N = 128; break;
        case 6: W = W6; N = 128; break;
        default: W = W7; N = 128; break;
    }
    int K = 32768 / N;
    int k = within / N, n = within % N;
    __half h = __float2half_rn(W[within]);
    wT[(m << 15) + n * K + k] = *reinterpret_cast<uint16_t*>(&h);
}

// ---------------- mma.sync helpers ------------------------------------------
__device__ __forceinline__ uint32_t smem_u32(const void* p) {
    uint32_t a;
    asm("{ .reg .u64 t; cvta.to.shared.u64 t, %1; cvt.u32.u64 %0, t; }"
        : "=r"(a) : "l"(p));
    return a;
}
__device__ __forceinline__ void ldm_x4(uint32_t addr, uint32_t& r0, uint32_t& r1,
                                       uint32_t& r2, uint32_t& r3) {
    asm volatile("ldmatrix.sync.aligned.m8n8.x4.shared.b16 {%0,%1,%2,%3}, [%4];"
                 : "=r"(r0), "=r"(r1), "=r"(r2), "=r"(r3) : "r"(addr));
}
__device__ __forceinline__ void mma_f16(float* c, const uint32_t* a,
                                        const uint32_t* b) {
    asm volatile(
        "mma.sync.aligned.m16n8k16.row.col.f32.f16.f16.f32 "
        "{%0,%1,%2,%3}, {%4,%5,%6,%7}, {%8,%9}, {%0,%1,%2,%3};"
        : "+f"(c[0]), "+f"(c[1]), "+f"(c[2]), "+f"(c[3])
        : "r"(a[0]), "r"(a[1]), "r"(a[2]), "r"(a[3]), "r"(b[0]), "r"(b[1]));
}
__device__ __forceinline__ void cp16(uint32_t dst, const void* src, int sz) {
    asm volatile("cp.async.cg.shared.global [%0], [%1], 16, %2;"
                 :: "r"(dst), "l"(src), "r"(sz) : "memory");
}

// ---------------- mega GEMM: L1 SAGE + combo projection fused ---------------
// BK=32 staging, double-buffered; SMEM sized for 2 CTAs/SM.
//  Stage A: h[128,256] = relu(A0@W1l + A1@W1r + b1), kept in SMEM (fp16).
//  Stage B: pf = fp16(h @ Wc[0:128]); r = h @ Wc[128:256] + b2 (fp32).
#define SROW2 40                     // staging: fp16/row (32 + 8 pad)
#define ATILE2 (128 * SROW2 * 2)     // 10240 B per operand tile
#define STAGE2 (2 * ATILE2)          // A + B per buffer = 20480
#define HROW 264                     // h smem row: 256 + 8 pad (fp16)
#define H_BYTES (128 * HROW * 2)     // 67584
#define MEGA_SMEM (H_BYTES + 2 * STAGE2)  // 108544 -> 2 CTAs/SM
__global__ void __launch_bounds__(256, 2)
mega_gemm(const uint16_t* __restrict__ A0, const uint16_t* __restrict__ A1,
          const uint16_t* __restrict__ W1l, const uint16_t* __restrict__ W1r,
          const float* __restrict__ b1,
          const uint16_t* __restrict__ Wc, const float* __restrict__ b2,
          uint16_t* __restrict__ Pf, float* __restrict__ R, int M) {
    extern __shared__ __align__(16) uint16_t smem[];
    const uint32_t hbase = smem_u32(smem);
    const uint32_t stage = hbase + H_BYTES;

    const int tid = threadIdx.x;
    const int wid = tid >> 5, lane = tid & 31;
    const int wm = wid >> 2, wn = wid & 3;
    const int rowBase = blockIdx.y * 128;

    // loader: 256 threads, tile = 128 rows x 32 fp16 = 512 segs of 16B
    const int ldR0 = tid >> 2;        // 0..63, rows step 64
    const int ldS = tid & 3;          // 4 segs of 8 fp16

    const int aRow = lane & 15, aColH = (lane >> 4) * 8;
    const int bRow = ((lane >> 4) & 1) * 8 + (lane & 7);
    const int bColH = ((lane >> 3) & 1) * 8;
    const int qr = lane >> 2, qc = lane & 3;

    float acc[4][4][4];

    // ================= Stage A: h = relu(A0@W1l + A1@W1r + b1) ==============
#pragma unroll 1
    for (int half = 0; half < 2; ++half) {
#pragma unroll
        for (int i = 0; i < 4; ++i)
#pragma unroll
            for (int j = 0; j < 4; ++j)
#pragma unroll
                for (int k = 0; k < 4; ++k) acc[i][j][k] = 0.f;

        auto issueA = [&](int c) {   // c in 0..7: phase = c>>2, k0 = (c&3)*32
            const int phase = c >> 2;
            const int k0 = (c & 3) * 32;
            const uint16_t* a = phase ? A1 : A0;
            const uint16_t* w = phase ? W1r : W1l;
            const uint32_t st = stage + (c & 1) * STAGE2;
#pragma unroll
            for (int it = 0; it < 2; ++it) {
                const int r = ldR0 + it * 64;
                const uint32_t doff = r * (SROW2 * 2) + ldS * 16;
                const int grow = rowBase + r;
                const int sz = (grow < M) ? 16 : 0;
                cp16(st + doff,
                     a + (size_t)(grow < M ? grow : 0) * 128 + k0 + ldS * 8, sz);
                cp16(st + ATILE2 + doff,
                     w + (size_t)(half * 128 + r) * 128 + k0 + ldS * 8, 16);
            }
            asm volatile("cp.async.commit_group;" ::: "memory");
        };

        issueA(0);
        issueA(1);
        for (int c = 0; c < 8; ++c) {
            if (c < 7) asm volatile("cp.async.wait_group 1;" ::: "memory");
            else       asm volatile("cp.async.wait_group 0;" ::: "memory");
            __syncthreads();
            const uint32_t st = stage + (c & 1) * STAGE2;
#pragma unroll
            for (int ks = 0; ks < 2; ++ks) {
                const int kk = ks * 16;
                uint32_t af[4][4];
#pragma unroll
                for (int fm = 0; fm < 4; ++fm) {
                    uint32_t off = st + 2u * ((wm * 64 + fm * 16 + aRow) * SROW2 + kk + aColH);
                    ldm_x4(off, af[fm][0], af[fm][1], af[fm][2], af[fm][3]);
                }
                uint32_t bf[4][2];
#pragma unroll
                for (int g = 0; g < 2; ++g) {
                    uint32_t off = st + ATILE2 +
                                   2u * ((wn * 32 + g * 16 + bRow) * SROW2 + kk + bColH);
                    ldm_x4(off, bf[2 * g][0], bf[2 * g][1],
                           bf[2 * g + 1][0], bf[2 * g + 1][1]);
                }
#pragma unroll
                for (int fm = 0; fm < 4; ++fm)
#pragma unroll
                    for (int fn = 0; fn < 4; ++fn)
                        mma_f16(acc[fm][fn], af[fm], bf[fn]);
            }
            __syncthreads();
            if (c + 2 < 8) issueA(c + 2);
        }

        // epilogue: relu(acc + b1) -> h smem (fp16)
#pragma unroll
        for (int fm = 0; fm < 4; ++fm) {
            const int row0 = wm * 64 + fm * 16 + qr;
#pragma unroll
            for (int fn = 0; fn < 4; ++fn) {
                const int colh = wn * 32 + fn * 8 + qc * 2;
                const int col = half * 128 + colh;
                const float bx = b1[col], by = b1[col + 1];
#pragma unroll
                for (int hh = 0; hh < 2; ++hh) {
                    const int row = row0 + hh * 8;
                    float vx = fmaxf(acc[fm][fn][hh * 2 + 0] + bx, 0.f);
                    float vy = fmaxf(acc[fm][fn][hh * 2 + 1] + by, 0.f);
                    __half2 hp = __float22half2_rn(make_float2(vx, vy));
                    uint32_t addr = hbase + 2u * (row * HROW + col);
                    asm volatile("st.shared.b32 [%0], %1;"
                                 :: "r"(addr), "r"(*reinterpret_cast<uint32_t*>(&hp))
                                 : "memory");
                }
            }
        }
    }
    __syncthreads();  // h complete

    // ================= Stage B: [pf | r] = h @ Wc ============================
#pragma unroll 1
    for (int half = 0; half < 2; ++half) {
#pragma unroll
        for (int i = 0; i < 4; ++i)
#pragma unroll
            for (int j = 0; j < 4; ++j)
#pragma unroll
                for (int k = 0; k < 4; ++k) acc[i][j][k] = 0.f;

        auto issueB = [&](int c) {   // c in 0..7: k0 = c*32 over K=256
            const int k0 = c * 32;
            const uint32_t st = stage + (c & 1) * STAGE2;
#pragma unroll
            for (int it = 0; it < 2; ++it) {
                const int r = ldR0 + it * 64;
                const uint32_t doff = r * (SROW2 * 2) + ldS * 16;
                cp16(st + ATILE2 + doff,
                     Wc + (size_t)(half * 128 + r) * 256 + k0 + ldS * 8, 16);
            }
            asm volatile("cp.async.commit_group;" ::: "memory");
        };

        issueB(0);
        issueB(1);
        for (int c = 0; c < 8; ++c) {
            if (c < 7) asm volatile("cp.async.wait_group 1;" ::: "memory");
            else       asm volatile("cp.async.wait_group 0;" ::: "memory");
            __syncthreads();
            const uint32_t st = stage + (c & 1) * STAGE2;
#pragma unroll
            for (int ks = 0; ks < 2; ++ks) {
                const int kkg = c * 32 + ks * 16;
                uint32_t af[4][4];
#pragma unroll
                for (int fm = 0; fm < 4; ++fm) {
                    uint32_t off = hbase + 2u * ((wm * 64 + fm * 16 + aRow) * HROW + kkg + aColH);
                    ldm_x4(off, af[fm][0], af[fm][1], af[fm][2], af[fm][3]);
                }
                uint32_t bf[4][2];
#pragma unroll
                for (int g = 0; g < 2; ++g) {
                    uint32_t off = st + ATILE2 +
                                   2u * ((wn * 32 + g * 16 + bRow) * SROW2 + ks * 16 + bColH);
                    ldm_x4(off, bf[2 * g][0], bf[2 * g][1],
                           bf[2 * g + 1][0], bf[2 * g + 1][1]);
                }
#pragma unroll
                for (int fm = 0; fm < 4; ++fm)
#pragma unroll
                    for (int fn = 0; fn < 4; ++fn)
                        mma_f16(acc[fm][fn], af[fm], bf[fn]);
            }
            __syncthreads();
            if (c + 2 < 8) issueB(c + 2);
        }

        // epilogue: half0 -> pf (fp16, no bias); half1 -> r (fp32, + b2)
#pragma unroll
        for (int fm = 0; fm < 4; ++fm) {
            const int r0 = rowBase + wm * 64 + fm * 16 + qr;
#pragma unroll
            for (int fn = 0; fn < 4; ++fn) {
                const int colh = wn * 32 + fn * 8 + qc * 2;
#pragma unroll
                for (int hh = 0; hh < 2; ++hh) {
                    const int rr = r0 + hh * 8;
                    if (rr >= M) continue;
                    float vx = acc[fm][fn][hh * 2 + 0];
                    float vy = acc[fm][fn][hh * 2 + 1];
                    if (half == 0) {
                        __half2 hp = __float22half2_rn(make_float2(vx, vy));
                        *(uint32_t*)(Pf + (size_t)rr * 128 + colh) =
                            *reinterpret_cast<uint32_t*>(&hp);
                    } else {
                        *(float2*)(R + (size_t)rr * 128 + colh) =
                            make_float2(vx + b2[colh], vy + b2[colh + 1]);
                    }
                }
            }
        }
    }
}

// ---------------- host launch ------------------------------------------------
static inline int cdiv(int a, int b) { return (a + b - 1) / b; }

extern "C" void kernel_launch(void* const* d_in, const int* in_sizes, int n_in,
                              void* d_out, int out_size) {
    const float* x_user = (const float*)d_in[0];
    const float* x_item = (const float*)d_in[1];
    const int* e_src = (const int*)d_in[2];
    const int* e_dst = (const int*)d_in[3];
    const float* Wl1_ui = (const float*)d_in[4];
    const float* Wr1_ui = (const float*)d_in[5];
    const float* bl1_ui = (const float*)d_in[6];
    const float* Wl1_iu = (const float*)d_in[7];
    const float* Wr1_iu = (const float*)d_in[8];
    const float* bl1_iu = (const float*)d_in[9];
    const float* Wl2_ui = (const float*)d_in[10];
    const float* Wr2_ui = (const float*)d_in[11];
    const float* bl2_ui = (const float*)d_in[12];
    const float* Wl2_iu = (const float*)d_in[13];
    const float* Wr2_iu = (const float*)d_in[14];
    const float* bl2_iu = (const float*)d_in[15];
    float* out = (float*)d_out;

    float *r_u, *r_i;
    int *cnt_u, *cnt_i, *adj_u, *adj_i;
    uint16_t *xf_u, *xf_i, *a1f_u, *a1f_i, *pf_u, *pf_i, *wT;
    cudaGetSymbolAddress((void**)&r_u, g_r_u);
    cudaGetSymbolAddress((void**)&r_i, g_r_i);
    cudaGetSymbolAddress((void**)&cnt_u, g_cnt_u);
    cudaGetSymbolAddress((void**)&cnt_i, g_cnt_i);
    cudaGetSymbolAddress((void**)&adj_u, g_adj_u);
    cudaGetSymbolAddress((void**)&adj_i, g_adj_i);
    cudaGetSymbolAddress((void**)&xf_u, g_xf_u);
    cudaGetSymbolAddress((void**)&xf_i, g_xf_i);
    cudaGetSymbolAddress((void**)&a1f_u, g_a1f_u);
    cudaGetSymbolAddress((void**)&a1f_i, g_a1f_i);
    cudaGetSymbolAddress((void**)&pf_u, g_pf_u);
    cudaGetSymbolAddress((void**)&pf_i, g_pf_i);
    cudaGetSymbolAddress((void**)&wT, g_wT);

    cudaFuncSetAttribute(mega_gemm, cudaFuncAttributeMaxDynamicSharedMemorySize,
                         MEGA_SMEM);

    const int TB = 256;

    // 1: x converts (merged)
    cvt2_kernel<<<cdiv((NUM_U + NUM_I) * 32, TB), TB>>>(
        (const float4*)x_user, (uint2*)xf_u, (const float4*)x_item, (uint2*)xf_i);
    // 2: cnt zero (merged)
    zero2_kernel<<<cdiv(NUM_U + NUM_I, TB), TB>>>(cnt_u, NUM_U, cnt_i, NUM_I);
    // 3: adjacency fill
    fill_adj<<<cdiv(NUM_E, TB), TB>>>(e_src, e_dst, cnt_u, cnt_i, adj_u, adj_i);
    // 4: weight prep (merged, 8 matrices)
    prep_all<<<cdiv(262144, TB), TB>>>(Wl1_ui, Wr1_ui, Wl1_iu, Wr1_iu,
                                       Wl2_ui, Wr2_iu, Wl2_iu, Wr2_ui, wT);
    // 5: layer-1 gather-mean, items + users in one launch
    gather2<<<cdiv((NUM_I + NUM_U) * 16, TB), TB>>>(
        xf_u, a1f_i, nullptr, nullptr,
        xf_i, a1f_u, nullptr, nullptr,
        adj_i, cnt_i, adj_u, cnt_u);
    // 6: mega GEMM items
    {
        dim3 gi(1, cdiv(NUM_I, 128));
        mega_gemm<<<gi, 256, MEGA_SMEM>>>(a1f_i, xf_i,
            wT + 0 * 32768, wT + 1 * 32768, bl1_ui,
            wT + 196608, bl2_ui, pf_i, r_i, NUM_I);
    }
    // 7: mega GEMM users
    {
        dim3 gu(1, cdiv(NUM_U, 128));
        mega_gemm<<<gu, 256, MEGA_SMEM>>>(a1f_u, xf_u,
            wT + 2 * 32768, wT + 3 * 32768, bl1_iu,
            wT + 131072, bl2_iu, pf_u, r_u, NUM_U);
    }
    // 8: layer-2 gather + add + relu, items + users in one launch
    gather2<<<cdiv((NUM_I + NUM_U) * 16, TB), TB>>>(
        pf_u, nullptr, out + (size_t)NUM_U * DIM_O, r_i,
        pf_i, nullptr, out, r_u,
        adj_i, cnt_i, adj_u, cnt_u);
}